// round 2
// baseline (speedup 1.0000x reference)
#include <cuda_runtime.h>
#include <cuda_bf16.h>
#include <stdint.h>

#define MAXN 100000
#define MAXE 1600000
#define HID  64

// ---------------- device scratch (no allocation allowed) ----------------
static __device__ __align__(256) float g_deg[MAXN];
static __device__ __align__(256) float g_dinv[MAXN];
static __device__ __align__(256) float g_h[(size_t)MAXN * HID];   // GEMM output
static __device__ __align__(256) float g_out[(size_t)MAXN * HID]; // aggregation target
static __device__ __align__(256) float g_a[(size_t)MAXN * HID];   // relu(out+b)

// ---------------- degree / norm ----------------
__global__ void k_init_deg(int n) {
    int i = blockIdx.x * blockDim.x + threadIdx.x;
    if (i < n) g_deg[i] = 1.0f;   // self loop
}

__global__ void k_count_deg(const int* __restrict__ dst, int e) {
    int i = blockIdx.x * blockDim.x + threadIdx.x;
    if (i < e) atomicAdd(&g_deg[dst[i]], 1.0f);
}

__global__ void k_dinv(int n) {
    int i = blockIdx.x * blockDim.x + threadIdx.x;
    if (i < n) g_dinv[i] = rsqrtf(g_deg[i]);
}

// ---------------- tiled GEMM: Y[n,64] = X[n,K] @ W[K,64] ----------------
// block = 256 threads (16x16), tile 64 rows x 64 cols, K processed in 64-chunks.
__global__ void k_gemm64(const float* __restrict__ X, const float* __restrict__ W,
                         float* __restrict__ Y, int n, int K) {
    __shared__ float sXT[64][68];   // [k][row], padded so rows are 16B-aligned
    __shared__ float sW[64][64];    // [k][col]

    const int tid = threadIdx.x;
    const int tx = tid & 15;        // col group
    const int ty = tid >> 4;        // row group
    const int rowBase = blockIdx.x * 64;

    float acc[4][4];
#pragma unroll
    for (int i = 0; i < 4; ++i)
#pragma unroll
        for (int j = 0; j < 4; ++j) acc[i][j] = 0.0f;

    const int nChunks = K >> 6;
    for (int c = 0; c < nChunks; ++c) {
        // load X chunk (64 rows x 64 k) transposed into sXT.
        for (int i = tid; i < 1024; i += 256) {
            int q = i >> 6, r = i & 63;
            int row = rowBase + r;
            float4 v = make_float4(0.f, 0.f, 0.f, 0.f);
            if (row < n)
                v = *(const float4*)(X + (size_t)row * K + (c << 6) + (q << 2));
            sXT[(q << 2) + 0][r] = v.x;
            sXT[(q << 2) + 1][r] = v.y;
            sXT[(q << 2) + 2][r] = v.z;
            sXT[(q << 2) + 3][r] = v.w;
        }
        // load W chunk (64 k x 64 cols)
        for (int i = tid; i < 1024; i += 256) {
            int r = i >> 4, q = i & 15;
            float4 v = *(const float4*)(W + (size_t)((c << 6) + r) * 64 + (q << 2));
            *(float4*)&sW[r][q << 2] = v;
        }
        __syncthreads();

#pragma unroll 16
        for (int kk = 0; kk < 64; ++kk) {
            float4 a = *(float4*)&sXT[kk][ty << 2];
            float4 b = *(float4*)&sW[kk][tx << 2];
            acc[0][0] += a.x * b.x; acc[0][1] += a.x * b.y; acc[0][2] += a.x * b.z; acc[0][3] += a.x * b.w;
            acc[1][0] += a.y * b.x; acc[1][1] += a.y * b.y; acc[1][2] += a.y * b.z; acc[1][3] += a.y * b.w;
            acc[2][0] += a.z * b.x; acc[2][1] += a.z * b.y; acc[2][2] += a.z * b.z; acc[2][3] += a.z * b.w;
            acc[3][0] += a.w * b.x; acc[3][1] += a.w * b.y; acc[3][2] += a.w * b.z; acc[3][3] += a.w * b.w;
        }
        __syncthreads();
    }

#pragma unroll
    for (int i = 0; i < 4; ++i) {
        int row = rowBase + (ty << 2) + i;
        if (row < n) {
#pragma unroll
            for (int j = 0; j < 4; ++j)
                Y[(size_t)row * 64 + (tx << 2) + j] = acc[i][j];
        }
    }
}

// ---------------- self-loop init: out[i] = dinv[i]^2 * h[i] ----------------
__global__ void k_selfloop(const float* __restrict__ h, float* __restrict__ out, int n) {
    int t = blockIdx.x * blockDim.x + threadIdx.x;
    if (t >= n * 16) return;
    int row = t >> 4;
    float s = g_dinv[row];
    float s2 = s * s;
    float4 v = *(const float4*)(h + ((size_t)t << 2));
    v.x *= s2; v.y *= s2; v.z *= s2; v.w *= s2;
    *(float4*)(out + ((size_t)t << 2)) = v;
}

// ---------------- edge scatter: out[dst] += dinv[src]*dinv[dst]*h[src] ----------------
// 16 threads per edge, one float4 each -> coalesced 256B gather per edge,
// fire-and-forget vector reductions (red.global.add.v4.f32).
__global__ void k_scatter(const int* __restrict__ src, const int* __restrict__ dst,
                          const float* __restrict__ h, float* __restrict__ out, int e) {
    int t = blockIdx.x * blockDim.x + threadIdx.x;
    int eid = t >> 4;
    if (eid >= e) return;
    int part = t & 15;
    int s = src[eid];
    int d = dst[eid];
    float nm = g_dinv[s] * g_dinv[d];
    float4 v = *(const float4*)(h + (size_t)s * 64 + (part << 2));
    v.x *= nm; v.y *= nm; v.z *= nm; v.w *= nm;
    float* p = out + (size_t)d * 64 + (part << 2);
    asm volatile("red.global.add.v4.f32 [%0], {%1, %2, %3, %4};"
                 :: "l"(p), "f"(v.x), "f"(v.y), "f"(v.z), "f"(v.w)
                 : "memory");
}

// ---------------- bias + relu ----------------
__global__ void k_bias_relu(const float* __restrict__ in, const float* __restrict__ bias,
                            float* __restrict__ out, int n) {
    int t = blockIdx.x * blockDim.x + threadIdx.x;
    if (t >= n * 16) return;
    int part = t & 15;
    float4 b = *(const float4*)(bias + (part << 2));
    float4 v = *(const float4*)(in + ((size_t)t << 2));
    v.x = fmaxf(v.x + b.x, 0.f);
    v.y = fmaxf(v.y + b.y, 0.f);
    v.z = fmaxf(v.z + b.z, 0.f);
    v.w = fmaxf(v.w + b.w, 0.f);
    *(float4*)(out + ((size_t)t << 2)) = v;
}

// ---------------- classifier: logits[i] = relu(out[i]+b2) . Wc + bc ----------------
// one warp per row
__global__ void k_classify(const float* __restrict__ in, const float* __restrict__ b2,
                           const float* __restrict__ Wc, const float* __restrict__ bc,
                           float* __restrict__ logits, int n) {
    int t = blockIdx.x * blockDim.x + threadIdx.x;
    int row = t >> 5;
    if (row >= n) return;
    int lane = t & 31;
    const float* r = in + (size_t)row * 64;
    float v0 = fmaxf(r[lane] + b2[lane], 0.f) * Wc[lane];
    float v1 = fmaxf(r[lane + 32] + b2[lane + 32], 0.f) * Wc[lane + 32];
    float sum = v0 + v1;
#pragma unroll
    for (int o = 16; o > 0; o >>= 1) sum += __shfl_xor_sync(0xffffffffu, sum, o);
    if (lane == 0) logits[row] = sum + bc[0];
}

// ---------------- launcher ----------------
extern "C" void kernel_launch(void* const* d_in, const int* in_sizes, int n_in,
                              void* d_out, int out_size) {
    const float* x  = (const float*)d_in[0];
    const int*   ei = (const int*)d_in[1];   // JAX default: int32 (x64 disabled)
    const float* W1 = (const float*)d_in[2];
    const float* b1 = (const float*)d_in[3];
    const float* W2 = (const float*)d_in[4];
    const float* b2 = (const float*)d_in[5];
    const float* Wc = (const float*)d_in[6];
    const float* bc = (const float*)d_in[7];
    float* logits = (float*)d_out;

    const int n = in_sizes[0] / 128;
    const int e = in_sizes[1] / 2;
    const int* src = ei;
    const int* dst = ei + e;

    float *p_h, *p_out, *p_a;
    cudaGetSymbolAddress((void**)&p_h,   g_h);
    cudaGetSymbolAddress((void**)&p_out, g_out);
    cudaGetSymbolAddress((void**)&p_a,   g_a);

    const int T = 256;
    // degree + norm
    k_init_deg<<<(n + T - 1) / T, T>>>(n);
    k_count_deg<<<(e + T - 1) / T, T>>>(dst, e);
    k_dinv<<<(n + T - 1) / T, T>>>(n);

    // layer 1
    k_gemm64<<<(n + 63) / 64, T>>>(x, W1, p_h, n, 128);
    k_selfloop<<<(n * 16 + T - 1) / T, T>>>(p_h, p_out, n);
    k_scatter<<<((e * 16) + T - 1) / T, T>>>(src, dst, p_h, p_out, e);
    k_bias_relu<<<(n * 16 + T - 1) / T, T>>>(p_out, b1, p_a, n);

    // layer 2
    k_gemm64<<<(n + 63) / 64, T>>>(p_a, W2, p_h, n, 64);
    k_selfloop<<<(n * 16 + T - 1) / T, T>>>(p_h, p_out, n);
    k_scatter<<<((e * 16) + T - 1) / T, T>>>(src, dst, p_h, p_out, e);

    // classifier (fuses bias2 + relu)
    k_classify<<<(n * 32 + T - 1) / T, T>>>(p_out, b2, Wc, bc, logits, n);
}

// round 3
// speedup vs baseline: 1.6009x; 1.6009x over previous
#include <cuda_runtime.h>
#include <cuda_bf16.h>
#include <stdint.h>

#define MAXN 100000
#define MAXE 1600000
#define HID  64
#define SCANB 1024
#define NBLK  ((MAXN + SCANB - 1) / SCANB)   // 98

// ---------------- device scratch ----------------
static __device__ __align__(256) int   g_cnt[MAXN];
static __device__ __align__(256) int   g_rowptr[MAXN + 1];
static __device__ __align__(256) int   g_cursor[MAXN];
static __device__ __align__(256) int   g_blksum[NBLK + 1];
static __device__ __align__(256) int   g_csr_src[MAXE];
static __device__ __align__(256) float g_dinv[MAXN];
static __device__ __align__(256) float g_hs[(size_t)MAXN * HID];  // dinv-scaled GEMM output
static __device__ __align__(256) float g_a[(size_t)MAXN * HID];   // layer-1 activations

// ---------------- CSR build ----------------
__global__ void k_zero(int n) {
    int i = blockIdx.x * blockDim.x + threadIdx.x;
    if (i < n) g_cnt[i] = 0;
}

__global__ void k_count(const int* __restrict__ dst, int e) {
    int i = blockIdx.x * blockDim.x + threadIdx.x;
    if (i < e) atomicAdd(&g_cnt[dst[i]], 1);
}

// per-block inclusive scan -> exclusive offsets + block totals
__global__ void k_scan_block(int n) {
    __shared__ int s[SCANB];
    int t = threadIdx.x;
    int i = blockIdx.x * SCANB + t;
    int v = (i < n) ? g_cnt[i] : 0;
    s[t] = v;
    __syncthreads();
#pragma unroll
    for (int off = 1; off < SCANB; off <<= 1) {
        int x = (t >= off) ? s[t - off] : 0;
        __syncthreads();
        s[t] += x;
        __syncthreads();
    }
    if (i < n) g_rowptr[i] = s[t] - v;          // block-local exclusive
    if (t == SCANB - 1) g_blksum[blockIdx.x] = s[t];
}

__global__ void k_scan_tops(int nb) {
    if (threadIdx.x == 0 && blockIdx.x == 0) {
        int run = 0;
        for (int j = 0; j < nb; ++j) {
            int t = g_blksum[j];
            g_blksum[j] = run;
            run += t;
        }
        g_blksum[nb] = run;
    }
}

// finalize rowptr, cursor, dinv
__global__ void k_finish_offsets(int n, int e) {
    int i = blockIdx.x * blockDim.x + threadIdx.x;
    if (i < n) {
        int r = g_rowptr[i] + g_blksum[i >> 10];
        g_rowptr[i] = r;
        g_cursor[i] = r;
        g_dinv[i]   = rsqrtf((float)g_cnt[i] + 1.0f);   // +1 self loop
        if (i == n - 1) g_rowptr[n] = e;
    }
}

__global__ void k_fill(const int* __restrict__ src, const int* __restrict__ dst, int e) {
    int i = blockIdx.x * blockDim.x + threadIdx.x;
    if (i < e) {
        int pos = atomicAdd(&g_cursor[dst[i]], 1);
        g_csr_src[pos] = src[i];
    }
}

// ---------------- GEMM: Y[row] = dinv[row] * (X[n,K] @ W[K,64]) ----------------
// 256 threads, tile 128 rows x 64 cols, per-thread 8x4 register tile.
__global__ void k_gemm(const float* __restrict__ X, const float* __restrict__ W,
                       float* __restrict__ Y, int n, int K) {
    __shared__ float sXT[64][132];   // [k][row], padded
    __shared__ float sW[64][64];     // [k][col]

    const int tid = threadIdx.x;
    const int tx = tid & 15;         // col group (4 cols)
    const int ty = tid >> 4;         // row group (8 rows)
    const int rowBase = blockIdx.x * 128;

    float acc[8][4];
#pragma unroll
    for (int i = 0; i < 8; ++i)
#pragma unroll
        for (int j = 0; j < 4; ++j) acc[i][j] = 0.0f;

    const int nChunks = K >> 6;
    for (int c = 0; c < nChunks; ++c) {
        // X chunk: 128 rows x 64 k, transposed into sXT
        for (int i = tid; i < 2048; i += 256) {
            int q = i >> 7, r = i & 127;
            int row = rowBase + r;
            float4 v = make_float4(0.f, 0.f, 0.f, 0.f);
            if (row < n)
                v = *(const float4*)(X + (size_t)row * K + (c << 6) + (q << 2));
            sXT[(q << 2) + 0][r] = v.x;
            sXT[(q << 2) + 1][r] = v.y;
            sXT[(q << 2) + 2][r] = v.z;
            sXT[(q << 2) + 3][r] = v.w;
        }
        // W chunk: 64 k x 64 cols
        for (int i = tid; i < 1024; i += 256) {
            int r = i >> 4, q = i & 15;
            *(float4*)&sW[r][q << 2] =
                *(const float4*)(W + (size_t)((c << 6) + r) * 64 + (q << 2));
        }
        __syncthreads();

#pragma unroll 8
        for (int kk = 0; kk < 64; ++kk) {
            float4 b  = *(float4*)&sW[kk][tx << 2];
            float4 a0 = *(float4*)&sXT[kk][ty << 3];
            float4 a1 = *(float4*)&sXT[kk][(ty << 3) + 4];
            acc[0][0] += a0.x * b.x; acc[0][1] += a0.x * b.y; acc[0][2] += a0.x * b.z; acc[0][3] += a0.x * b.w;
            acc[1][0] += a0.y * b.x; acc[1][1] += a0.y * b.y; acc[1][2] += a0.y * b.z; acc[1][3] += a0.y * b.w;
            acc[2][0] += a0.z * b.x; acc[2][1] += a0.z * b.y; acc[2][2] += a0.z * b.z; acc[2][3] += a0.z * b.w;
            acc[3][0] += a0.w * b.x; acc[3][1] += a0.w * b.y; acc[3][2] += a0.w * b.z; acc[3][3] += a0.w * b.w;
            acc[4][0] += a1.x * b.x; acc[4][1] += a1.x * b.y; acc[4][2] += a1.x * b.z; acc[4][3] += a1.x * b.w;
            acc[5][0] += a1.y * b.x; acc[5][1] += a1.y * b.y; acc[5][2] += a1.y * b.z; acc[5][3] += a1.y * b.w;
            acc[6][0] += a1.z * b.x; acc[6][1] += a1.z * b.y; acc[6][2] += a1.z * b.z; acc[6][3] += a1.z * b.w;
            acc[7][0] += a1.w * b.x; acc[7][1] += a1.w * b.y; acc[7][2] += a1.w * b.z; acc[7][3] += a1.w * b.w;
        }
        __syncthreads();
    }

#pragma unroll
    for (int i = 0; i < 8; ++i) {
        int row = rowBase + (ty << 3) + i;
        if (row < n) {
            float s = g_dinv[row];
            float4 v = make_float4(acc[i][0] * s, acc[i][1] * s, acc[i][2] * s, acc[i][3] * s);
            *(float4*)(Y + (size_t)row * 64 + (tx << 2)) = v;
        }
    }
}

// ---------------- pull aggregation, layer 1: a[d] = relu(dinv[d]*(hs[d]+sum hs[src]) + b1) ----------------
// one warp per node; each lane owns 2 floats (float2) of the 64-wide row.
__global__ void k_agg1(const float* __restrict__ hs, float* __restrict__ a,
                       const float* __restrict__ b1, int n) {
    int w = (blockIdx.x * blockDim.x + threadIdx.x) >> 5;
    if (w >= n) return;
    int lane = threadIdx.x & 31;

    float2 acc = *(const float2*)(hs + (size_t)w * 64 + (lane << 1));  // self term
    int i   = g_rowptr[w];
    int end = g_rowptr[w + 1];
    while (i < end) {
        int m = min(32, end - i);
        int sreg = (lane < m) ? g_csr_src[i + lane] : 0;
#pragma unroll 4
        for (int j = 0; j < m; ++j) {
            int s = __shfl_sync(0xffffffffu, sreg, j);
            float2 v = *(const float2*)(hs + (size_t)s * 64 + (lane << 1));
            acc.x += v.x; acc.y += v.y;
        }
        i += m;
    }
    float dv = g_dinv[w];
    float2 b = *(const float2*)(b1 + (lane << 1));
    float2 o;
    o.x = fmaxf(acc.x * dv + b.x, 0.f);
    o.y = fmaxf(acc.y * dv + b.y, 0.f);
    *(float2*)(a + (size_t)w * 64 + (lane << 1)) = o;
}

// ---------------- pull aggregation, layer 2 + classifier ----------------
// logits[d] = sum_c relu(dinv[d]*(hs[d]+sum hs[src])[c] + b2[c]) * Wc[c] + bc
__global__ void k_agg2(const float* __restrict__ hs,
                       const float* __restrict__ b2, const float* __restrict__ Wc,
                       const float* __restrict__ bc, float* __restrict__ logits, int n) {
    int w = (blockIdx.x * blockDim.x + threadIdx.x) >> 5;
    if (w >= n) return;
    int lane = threadIdx.x & 31;

    float2 acc = *(const float2*)(hs + (size_t)w * 64 + (lane << 1));
    int i   = g_rowptr[w];
    int end = g_rowptr[w + 1];
    while (i < end) {
        int m = min(32, end - i);
        int sreg = (lane < m) ? g_csr_src[i + lane] : 0;
#pragma unroll 4
        for (int j = 0; j < m; ++j) {
            int s = __shfl_sync(0xffffffffu, sreg, j);
            float2 v = *(const float2*)(hs + (size_t)s * 64 + (lane << 1));
            acc.x += v.x; acc.y += v.y;
        }
        i += m;
    }
    float dv = g_dinv[w];
    float2 b  = *(const float2*)(b2 + (lane << 1));
    float2 wc = *(const float2*)(Wc + (lane << 1));
    float sum = fmaxf(acc.x * dv + b.x, 0.f) * wc.x +
                fmaxf(acc.y * dv + b.y, 0.f) * wc.y;
#pragma unroll
    for (int o = 16; o > 0; o >>= 1) sum += __shfl_xor_sync(0xffffffffu, sum, o);
    if (lane == 0) logits[w] = sum + bc[0];
}

// ---------------- launcher ----------------
extern "C" void kernel_launch(void* const* d_in, const int* in_sizes, int n_in,
                              void* d_out, int out_size) {
    const float* x  = (const float*)d_in[0];
    const int*   ei = (const int*)d_in[1];   // int32 (JAX x64 disabled)
    const float* W1 = (const float*)d_in[2];
    const float* b1 = (const float*)d_in[3];
    const float* W2 = (const float*)d_in[4];
    const float* b2 = (const float*)d_in[5];
    const float* Wc = (const float*)d_in[6];
    const float* bc = (const float*)d_in[7];
    float* logits = (float*)d_out;

    const int n = in_sizes[0] / 128;
    const int e = in_sizes[1] / 2;
    const int* src = ei;
    const int* dst = ei + e;

    float *p_hs, *p_a;
    cudaGetSymbolAddress((void**)&p_hs, g_hs);
    cudaGetSymbolAddress((void**)&p_a,  g_a);

    const int T = 256;
    const int nb = (n + SCANB - 1) / SCANB;

    // CSR build + norms
    k_zero<<<(n + T - 1) / T, T>>>(n);
    k_count<<<(e + T - 1) / T, T>>>(dst, e);
    k_scan_block<<<nb, SCANB>>>(n);
    k_scan_tops<<<1, 32>>>(nb);
    k_finish_offsets<<<(n + T - 1) / T, T>>>(n, e);
    k_fill<<<(e + T - 1) / T, T>>>(src, dst, e);

    // layer 1
    k_gemm<<<(n + 127) / 128, T>>>(x, W1, p_hs, n, 128);
    k_agg1<<<(n * 32 + T - 1) / T, T>>>(p_hs, p_a, b1, n);

    // layer 2 + classifier
    k_gemm<<<(n + 127) / 128, T>>>(p_a, W2, p_hs, n, 64);
    k_agg2<<<(n * 32 + T - 1) / T, T>>>(p_hs, b2, Wc, bc, logits, n);
}

// round 4
// speedup vs baseline: 1.6483x; 1.0296x over previous
#include <cuda_runtime.h>
#include <cuda_fp16.h>
#include <stdint.h>

#define MAXN 100000
#define MAXE 1600000
#define HID  64
#define SCANB 1024
#define NBLK  ((MAXN + SCANB - 1) / SCANB)   // 98

// ---------------- device scratch ----------------
static __device__ __align__(256) int    g_cnt[MAXN];
static __device__ __align__(256) int    g_rowptr[MAXN + 1];
static __device__ __align__(256) int    g_cursor[MAXN];
static __device__ __align__(256) int    g_blksum[NBLK + 1];
static __device__ __align__(256) int    g_csr_src[MAXE];
static __device__ __align__(256) float  g_dinv[MAXN];
static __device__ __align__(256) __half g_hs[(size_t)MAXN * HID]; // dinv-scaled GEMM output (fp16)
static __device__ __align__(256) float  g_a[(size_t)MAXN * HID];  // layer-1 activations (fp32)

// ---------------- CSR build ----------------
__global__ void k_zero(int n) {
    int i = blockIdx.x * blockDim.x + threadIdx.x;
    if (i < n) g_cnt[i] = 0;
}

__global__ void k_count(const int* __restrict__ dst, int e) {
    int i = blockIdx.x * blockDim.x + threadIdx.x;
    if (i < e) atomicAdd(&g_cnt[dst[i]], 1);
}

// per-block inclusive scan -> exclusive offsets + block totals
__global__ void k_scan_block(int n) {
    __shared__ int s[SCANB];
    int t = threadIdx.x;
    int i = blockIdx.x * SCANB + t;
    int v = (i < n) ? g_cnt[i] : 0;
    s[t] = v;
    __syncthreads();
#pragma unroll
    for (int off = 1; off < SCANB; off <<= 1) {
        int x = (t >= off) ? s[t - off] : 0;
        __syncthreads();
        s[t] += x;
        __syncthreads();
    }
    if (i < n) g_rowptr[i] = s[t] - v;          // block-local exclusive
    if (t == SCANB - 1) g_blksum[blockIdx.x] = s[t];
}

// parallel exclusive scan of the (<=128) block sums
__global__ void k_scan_tops(int nb) {
    __shared__ int s[128];
    int t = threadIdx.x;
    int v = (t < nb) ? g_blksum[t] : 0;
    s[t] = v;
    __syncthreads();
#pragma unroll
    for (int off = 1; off < 128; off <<= 1) {
        int x = (t >= off) ? s[t - off] : 0;
        __syncthreads();
        s[t] += x;
        __syncthreads();
    }
    if (t < nb) g_blksum[t] = s[t] - v;         // exclusive
    if (t == nb - 1) g_blksum[nb] = s[t];
}

// finalize rowptr, cursor, dinv
__global__ void k_finish_offsets(int n, int e) {
    int i = blockIdx.x * blockDim.x + threadIdx.x;
    if (i < n) {
        int r = g_rowptr[i] + g_blksum[i >> 10];
        g_rowptr[i] = r;
        g_cursor[i] = r;
        g_dinv[i]   = rsqrtf((float)g_cnt[i] + 1.0f);   // +1 self loop
        if (i == n - 1) g_rowptr[n] = e;
    }
}

__global__ void k_fill(const int* __restrict__ src, const int* __restrict__ dst, int e) {
    int i = blockIdx.x * blockDim.x + threadIdx.x;
    if (i < e) {
        int pos = atomicAdd(&g_cursor[dst[i]], 1);
        g_csr_src[pos] = src[i];
    }
}

// ---------------- GEMM: Y[row] = half( dinv[row] * (X[n,K] @ W[K,64]) ) ----------------
// 256 threads, tile 128 rows x 64 cols, per-thread 8x4 register tile.
__global__ void k_gemm(const float* __restrict__ X, const float* __restrict__ W,
                       __half* __restrict__ Y, int n, int K) {
    __shared__ float sXT[64][132];   // [k][row], padded
    __shared__ float sW[64][64];     // [k][col]

    const int tid = threadIdx.x;
    const int tx = tid & 15;         // col group (4 cols)
    const int ty = tid >> 4;         // row group (8 rows)
    const int rowBase = blockIdx.x * 128;

    float acc[8][4];
#pragma unroll
    for (int i = 0; i < 8; ++i)
#pragma unroll
        for (int j = 0; j < 4; ++j) acc[i][j] = 0.0f;

    const int nChunks = K >> 6;
    for (int c = 0; c < nChunks; ++c) {
        for (int i = tid; i < 2048; i += 256) {
            int q = i >> 7, r = i & 127;
            int row = rowBase + r;
            float4 v = make_float4(0.f, 0.f, 0.f, 0.f);
            if (row < n)
                v = *(const float4*)(X + (size_t)row * K + (c << 6) + (q << 2));
            sXT[(q << 2) + 0][r] = v.x;
            sXT[(q << 2) + 1][r] = v.y;
            sXT[(q << 2) + 2][r] = v.z;
            sXT[(q << 2) + 3][r] = v.w;
        }
        for (int i = tid; i < 1024; i += 256) {
            int r = i >> 4, q = i & 15;
            *(float4*)&sW[r][q << 2] =
                *(const float4*)(W + (size_t)((c << 6) + r) * 64 + (q << 2));
        }
        __syncthreads();

#pragma unroll 8
        for (int kk = 0; kk < 64; ++kk) {
            float4 b  = *(float4*)&sW[kk][tx << 2];
            float4 a0 = *(float4*)&sXT[kk][ty << 3];
            float4 a1 = *(float4*)&sXT[kk][(ty << 3) + 4];
            acc[0][0] += a0.x * b.x; acc[0][1] += a0.x * b.y; acc[0][2] += a0.x * b.z; acc[0][3] += a0.x * b.w;
            acc[1][0] += a0.y * b.x; acc[1][1] += a0.y * b.y; acc[1][2] += a0.y * b.z; acc[1][3] += a0.y * b.w;
            acc[2][0] += a0.z * b.x; acc[2][1] += a0.z * b.y; acc[2][2] += a0.z * b.z; acc[2][3] += a0.z * b.w;
            acc[3][0] += a0.w * b.x; acc[3][1] += a0.w * b.y; acc[3][2] += a0.w * b.z; acc[3][3] += a0.w * b.w;
            acc[4][0] += a1.x * b.x; acc[4][1] += a1.x * b.y; acc[4][2] += a1.x * b.z; acc[4][3] += a1.x * b.w;
            acc[5][0] += a1.y * b.x; acc[5][1] += a1.y * b.y; acc[5][2] += a1.y * b.z; acc[5][3] += a1.y * b.w;
            acc[6][0] += a1.z * b.x; acc[6][1] += a1.z * b.y; acc[6][2] += a1.z * b.z; acc[6][3] += a1.z * b.w;
            acc[7][0] += a1.w * b.x; acc[7][1] += a1.w * b.y; acc[7][2] += a1.w * b.z; acc[7][3] += a1.w * b.w;
        }
        __syncthreads();
    }

#pragma unroll
    for (int i = 0; i < 8; ++i) {
        int row = rowBase + (ty << 3) + i;
        if (row < n) {
            float s = g_dinv[row];
            __half2 h0 = __floats2half2_rn(acc[i][0] * s, acc[i][1] * s);
            __half2 h1 = __floats2half2_rn(acc[i][2] * s, acc[i][3] * s);
            *(__half2*)(Y + (size_t)row * 64 + (tx << 2))     = h0;
            *(__half2*)(Y + (size_t)row * 64 + (tx << 2) + 2) = h1;
        }
    }
}

// ---------------- pull aggregation, layer 1 ----------------
// a[d] = relu(dinv[d]*(hs[d]+sum hs[src]) + b1); one warp/node, lane owns 2 channels.
__global__ void k_agg1(const __half* __restrict__ hs, float* __restrict__ a,
                       const float* __restrict__ b1, int n) {
    int w = (blockIdx.x * blockDim.x + threadIdx.x) >> 5;
    if (w >= n) return;
    int lane = threadIdx.x & 31;

    float2 self = __half22float2(*(const __half2*)(hs + (size_t)w * 64 + (lane << 1)));
    float2 acc = self;
    int i   = g_rowptr[w];
    int end = g_rowptr[w + 1];
    while (i < end) {
        int m = min(32, end - i);
        int sreg = (lane < m) ? g_csr_src[i + lane] : 0;
#pragma unroll 4
        for (int j = 0; j < m; ++j) {
            int s = __shfl_sync(0xffffffffu, sreg, j);
            float2 v = __half22float2(*(const __half2*)(hs + (size_t)s * 64 + (lane << 1)));
            acc.x += v.x; acc.y += v.y;
        }
        i += m;
    }
    float dv = g_dinv[w];
    float2 b = *(const float2*)(b1 + (lane << 1));
    float2 o;
    o.x = fmaxf(acc.x * dv + b.x, 0.f);
    o.y = fmaxf(acc.y * dv + b.y, 0.f);
    *(float2*)(a + (size_t)w * 64 + (lane << 1)) = o;
}

// ---------------- pull aggregation, layer 2 + classifier ----------------
__global__ void k_agg2(const __half* __restrict__ hs,
                       const float* __restrict__ b2, const float* __restrict__ Wc,
                       const float* __restrict__ bc, float* __restrict__ logits, int n) {
    int w = (blockIdx.x * blockDim.x + threadIdx.x) >> 5;
    if (w >= n) return;
    int lane = threadIdx.x & 31;

    float2 acc = __half22float2(*(const __half2*)(hs + (size_t)w * 64 + (lane << 1)));
    int i   = g_rowptr[w];
    int end = g_rowptr[w + 1];
    while (i < end) {
        int m = min(32, end - i);
        int sreg = (lane < m) ? g_csr_src[i + lane] : 0;
#pragma unroll 4
        for (int j = 0; j < m; ++j) {
            int s = __shfl_sync(0xffffffffu, sreg, j);
            float2 v = __half22float2(*(const __half2*)(hs + (size_t)s * 64 + (lane << 1)));
            acc.x += v.x; acc.y += v.y;
        }
        i += m;
    }
    float dv = g_dinv[w];
    float2 b  = *(const float2*)(b2 + (lane << 1));
    float2 wc = *(const float2*)(Wc + (lane << 1));
    float sum = fmaxf(acc.x * dv + b.x, 0.f) * wc.x +
                fmaxf(acc.y * dv + b.y, 0.f) * wc.y;
#pragma unroll
    for (int o = 16; o > 0; o >>= 1) sum += __shfl_xor_sync(0xffffffffu, sum, o);
    if (lane == 0) logits[w] = sum + bc[0];
}

// ---------------- launcher ----------------
extern "C" void kernel_launch(void* const* d_in, const int* in_sizes, int n_in,
                              void* d_out, int out_size) {
    const float* x  = (const float*)d_in[0];
    const int*   ei = (const int*)d_in[1];   // int32 (JAX x64 disabled)
    const float* W1 = (const float*)d_in[2];
    const float* b1 = (const float*)d_in[3];
    const float* W2 = (const float*)d_in[4];
    const float* b2 = (const float*)d_in[5];
    const float* Wc = (const float*)d_in[6];
    const float* bc = (const float*)d_in[7];
    float* logits = (float*)d_out;

    const int n = in_sizes[0] / 128;
    const int e = in_sizes[1] / 2;
    const int* src = ei;
    const int* dst = ei + e;

    __half* p_hs;
    float*  p_a;
    cudaGetSymbolAddress((void**)&p_hs, g_hs);
    cudaGetSymbolAddress((void**)&p_a,  g_a);

    const int T = 256;
    const int nb = (n + SCANB - 1) / SCANB;

    // CSR build + norms
    k_zero<<<(n + T - 1) / T, T>>>(n);
    k_count<<<(e + T - 1) / T, T>>>(dst, e);
    k_scan_block<<<nb, SCANB>>>(n);
    k_scan_tops<<<1, 128>>>(nb);
    k_finish_offsets<<<(n + T - 1) / T, T>>>(n, e);
    k_fill<<<(e + T - 1) / T, T>>>(src, dst, e);

    // layer 1
    k_gemm<<<(n + 127) / 128, T>>>(x, W1, p_hs, n, 128);
    k_agg1<<<(n * 32 + T - 1) / T, T>>>(p_hs, p_a, b1, n);

    // layer 2 + classifier
    k_gemm<<<(n + 127) / 128, T>>>(p_a, W2, p_hs, n, 64);
    k_agg2<<<(n * 32 + T - 1) / T, T>>>(p_hs, b2, Wc, bc, logits, n);
}

// round 5
// speedup vs baseline: 2.1581x; 1.3093x over previous
#include <cuda_runtime.h>
#include <cuda_fp16.h>
#include <mma.h>
#include <stdint.h>

using namespace nvcuda;

#define MAXN 100000
#define MAXE 1600000
#define HID  64
#define SCANB 1024
#define NBLK  ((MAXN + SCANB - 1) / SCANB)   // 98

// ---------------- device scratch (zero-initialized at module load) ----------------
static __device__ __align__(256) int    g_cnt[MAXN];          // must be 0 at entry; re-zeroed by k_finish
static __device__ __align__(256) int    g_rowptr[MAXN + 1];
static __device__ __align__(256) int    g_cursor[MAXN];
static __device__ __align__(256) int    g_blksum[NBLK + 1];
static __device__ __align__(256) int    g_csr_src[MAXE];
static __device__ __align__(256) float  g_dinv[MAXN];
static __device__ __align__(256) __half g_hs[(size_t)MAXN * HID]; // dinv-scaled GEMM output (fp16)
static __device__ __align__(256) float  g_a[(size_t)MAXN * HID];  // layer-1 activations (fp32)

// ---------------- CSR build ----------------
__global__ void k_count(const int* __restrict__ dst, int e) {
    int i = blockIdx.x * blockDim.x + threadIdx.x;
    if (i < e) atomicAdd(&g_cnt[dst[i]], 1);
}

// per-block exclusive offsets + block totals (warp-shuffle scan, 2 barriers)
__global__ void k_scan_block(int n) {
    __shared__ int warpsum[32];
    int t = threadIdx.x;
    int lane = t & 31, wid = t >> 5;
    int i = blockIdx.x * SCANB + t;
    int v = (i < n) ? g_cnt[i] : 0;
    int x = v;
#pragma unroll
    for (int o = 1; o < 32; o <<= 1) {
        int y = __shfl_up_sync(0xffffffffu, x, o);
        if (lane >= o) x += y;
    }
    if (lane == 31) warpsum[wid] = x;
    __syncthreads();
    if (t < 32) {
        int s = warpsum[t];
        int sx = s;
#pragma unroll
        for (int o = 1; o < 32; o <<= 1) {
            int y = __shfl_up_sync(0xffffffffu, sx, o);
            if (t >= o) sx += y;
        }
        warpsum[t] = sx - s;   // exclusive warp offsets
    }
    __syncthreads();
    int incl = x + warpsum[wid];
    if (i < n) g_rowptr[i] = incl - v;           // block-local exclusive
    if (t == SCANB - 1) g_blksum[blockIdx.x] = incl;  // block total
}

__global__ void k_dinv(int n) {
    int i = blockIdx.x * blockDim.x + threadIdx.x;
    if (i < n) g_dinv[i] = rsqrtf((float)g_cnt[i] + 1.0f);   // +1 self loop
}

// parallel exclusive scan of the (<=128) block sums
__global__ void k_scan_tops(int nb) {
    __shared__ int s[128];
    int t = threadIdx.x;
    int v = (t < nb) ? g_blksum[t] : 0;
    s[t] = v;
    __syncthreads();
#pragma unroll
    for (int off = 1; off < 128; off <<= 1) {
        int x = (t >= off) ? s[t - off] : 0;
        __syncthreads();
        s[t] += x;
        __syncthreads();
    }
    if (t < nb) g_blksum[t] = s[t] - v;         // exclusive
    if (t == nb - 1) g_blksum[nb] = s[t];
}

// finalize rowptr + cursor; re-zero g_cnt for the next call (replay determinism)
__global__ void k_finish_offsets(int n, int e) {
    int i = blockIdx.x * blockDim.x + threadIdx.x;
    if (i < n) {
        int r = g_rowptr[i] + g_blksum[i >> 10];
        g_rowptr[i] = r;
        g_cursor[i] = r;
        g_cnt[i]    = 0;
        if (i == n - 1) g_rowptr[n] = e;
    }
}

__global__ void k_fill(const int* __restrict__ src, const int* __restrict__ dst, int e) {
    int i = blockIdx.x * blockDim.x + threadIdx.x;
    if (i < e) {
        int pos = atomicAdd(&g_cursor[dst[i]], 1);
        g_csr_src[pos] = src[i];
    }
}

// ---------------- wmma GEMM: hs[row] = half( dinv[row] * (X[n,K] @ W[K,64]) ) ----------------
// 256 threads (8 warps), tile 128 rows x 64 cols. fp16 inputs (converted on stage-in),
// fp32 accumulate via HMMA m16n16k16. K chunked by 64.
__global__ void k_gemm_f16(const float* __restrict__ X, const float* __restrict__ W,
                           __half* __restrict__ Y, int n, int K) {
    // union: staging (sA 128x72 half, sB 64x72 half) vs epilogue (sOut 128x68 float)
    __shared__ __align__(16) unsigned char smbuf[34816];
    __half (*sA)[72]  = (__half(*)[72])smbuf;
    __half (*sB)[72]  = (__half(*)[72])(smbuf + 18432);
    float  (*sOut)[68] = (float(*)[68])smbuf;

    const int tid = threadIdx.x;
    const int wid = tid >> 5;
    const int wr = wid >> 1;          // 0..3 : 32-row band
    const int wc = wid & 1;           // 0..1 : 32-col band
    const int rowBase = blockIdx.x * 128;

    wmma::fragment<wmma::accumulator, 16, 16, 16, float> acc[2][2];
#pragma unroll
    for (int i = 0; i < 2; ++i)
#pragma unroll
        for (int j = 0; j < 2; ++j) wmma::fill_fragment(acc[i][j], 0.0f);

    const int nChunks = K >> 6;
    for (int c = 0; c < nChunks; ++c) {
        // stage X chunk: 128 rows x 64 k, fp32 -> fp16
        for (int i = tid; i < 2048; i += 256) {        // 2048 float4 loads
            int r = i >> 4, q = i & 15;
            int row = rowBase + r;
            float4 v = make_float4(0.f, 0.f, 0.f, 0.f);
            if (row < n)
                v = *(const float4*)(X + (size_t)row * K + (c << 6) + (q << 2));
            *(__half2*)&sA[r][(q << 2)]     = __floats2half2_rn(v.x, v.y);
            *(__half2*)&sA[r][(q << 2) + 2] = __floats2half2_rn(v.z, v.w);
        }
        // stage W chunk: 64 k x 64 cols, fp32 -> fp16
        for (int i = tid; i < 1024; i += 256) {
            int r = i >> 4, q = i & 15;
            float4 v = *(const float4*)(W + (size_t)((c << 6) + r) * 64 + (q << 2));
            *(__half2*)&sB[r][(q << 2)]     = __floats2half2_rn(v.x, v.y);
            *(__half2*)&sB[r][(q << 2) + 2] = __floats2half2_rn(v.z, v.w);
        }
        __syncthreads();

#pragma unroll
        for (int kk = 0; kk < 64; kk += 16) {
            wmma::fragment<wmma::matrix_a, 16, 16, 16, __half, wmma::row_major> a0, a1;
            wmma::fragment<wmma::matrix_b, 16, 16, 16, __half, wmma::row_major> b0, b1;
            wmma::load_matrix_sync(a0, &sA[wr * 32][kk], 72);
            wmma::load_matrix_sync(a1, &sA[wr * 32 + 16][kk], 72);
            wmma::load_matrix_sync(b0, &sB[kk][wc * 32], 72);
            wmma::load_matrix_sync(b1, &sB[kk][wc * 32 + 16], 72);
            wmma::mma_sync(acc[0][0], a0, b0, acc[0][0]);
            wmma::mma_sync(acc[0][1], a0, b1, acc[0][1]);
            wmma::mma_sync(acc[1][0], a1, b0, acc[1][0]);
            wmma::mma_sync(acc[1][1], a1, b1, acc[1][1]);
        }
        __syncthreads();
    }

    // write accumulators to smem (aliases sA/sB — synced above)
#pragma unroll
    for (int i = 0; i < 2; ++i)
#pragma unroll
        for (int j = 0; j < 2; ++j)
            wmma::store_matrix_sync(&sOut[wr * 32 + i * 16][wc * 32 + j * 16],
                                    acc[i][j], 68, wmma::mem_row_major);
    __syncthreads();

    // epilogue: scale by dinv[row], convert to fp16, store. 2 threads per row.
    {
        int r = tid >> 1;
        int cb = (tid & 1) << 5;
        int row = rowBase + r;
        if (row < n) {
            float s = g_dinv[row];
#pragma unroll
            for (int jj = 0; jj < 4; ++jj) {
                float4 v0 = *(float4*)&sOut[r][cb + (jj << 3)];
                float4 v1 = *(float4*)&sOut[r][cb + (jj << 3) + 4];
                __half2 h[4];
                h[0] = __floats2half2_rn(v0.x * s, v0.y * s);
                h[1] = __floats2half2_rn(v0.z * s, v0.w * s);
                h[2] = __floats2half2_rn(v1.x * s, v1.y * s);
                h[3] = __floats2half2_rn(v1.z * s, v1.w * s);
                *(uint4*)(Y + (size_t)row * 64 + cb + (jj << 3)) = *(uint4*)h;
            }
        }
    }
}

// ---------------- pull aggregation, layer 1 ----------------
// a[d] = relu(dinv[d]*(hs[d]+sum hs[src]) + b1); one warp/node, lane owns 2 channels.
__global__ void k_agg1(const __half* __restrict__ hs, float* __restrict__ a,
                       const float* __restrict__ b1, int n) {
    int w = (blockIdx.x * blockDim.x + threadIdx.x) >> 5;
    if (w >= n) return;
    int lane = threadIdx.x & 31;

    float2 acc = __half22float2(*(const __half2*)(hs + (size_t)w * 64 + (lane << 1)));
    int i   = g_rowptr[w];
    int end = g_rowptr[w + 1];
    while (i < end) {
        int m = min(32, end - i);
        int sreg = (lane < m) ? g_csr_src[i + lane] : 0;
        for (int j = 0; j < m; ++j) {
            int s = __shfl_sync(0xffffffffu, sreg, j);
            float2 v = __half22float2(*(const __half2*)(hs + (size_t)s * 64 + (lane << 1)));
            acc.x += v.x; acc.y += v.y;
        }
        i += m;
    }
    float dv = g_dinv[w];
    float2 b = *(const float2*)(b1 + (lane << 1));
    float2 o;
    o.x = fmaxf(acc.x * dv + b.x, 0.f);
    o.y = fmaxf(acc.y * dv + b.y, 0.f);
    *(float2*)(a + (size_t)w * 64 + (lane << 1)) = o;
}

// ---------------- pull aggregation, layer 2 + classifier ----------------
__global__ void k_agg2(const __half* __restrict__ hs,
                       const float* __restrict__ b2, const float* __restrict__ Wc,
                       const float* __restrict__ bc, float* __restrict__ logits, int n) {
    int w = (blockIdx.x * blockDim.x + threadIdx.x) >> 5;
    if (w >= n) return;
    int lane = threadIdx.x & 31;

    float2 acc = __half22float2(*(const __half2*)(hs + (size_t)w * 64 + (lane << 1)));
    int i   = g_rowptr[w];
    int end = g_rowptr[w + 1];
    while (i < end) {
        int m = min(32, end - i);
        int sreg = (lane < m) ? g_csr_src[i + lane] : 0;
        for (int j = 0; j < m; ++j) {
            int s = __shfl_sync(0xffffffffu, sreg, j);
            float2 v = __half22float2(*(const __half2*)(hs + (size_t)s * 64 + (lane << 1)));
            acc.x += v.x; acc.y += v.y;
        }
        i += m;
    }
    float dv = g_dinv[w];
    float2 b  = *(const float2*)(b2 + (lane << 1));
    float2 wc = *(const float2*)(Wc + (lane << 1));
    float sum = fmaxf(acc.x * dv + b.x, 0.f) * wc.x +
                fmaxf(acc.y * dv + b.y, 0.f) * wc.y;
#pragma unroll
    for (int o = 16; o > 0; o >>= 1) sum += __shfl_xor_sync(0xffffffffu, sum, o);
    if (lane == 0) logits[w] = sum + bc[0];
}

// ---------------- launcher ----------------
extern "C" void kernel_launch(void* const* d_in, const int* in_sizes, int n_in,
                              void* d_out, int out_size) {
    const float* x  = (const float*)d_in[0];
    const int*   ei = (const int*)d_in[1];   // int32 (JAX x64 disabled)
    const float* W1 = (const float*)d_in[2];
    const float* b1 = (const float*)d_in[3];
    const float* W2 = (const float*)d_in[4];
    const float* b2 = (const float*)d_in[5];
    const float* Wc = (const float*)d_in[6];
    const float* bc = (const float*)d_in[7];
    float* logits = (float*)d_out;

    const int n = in_sizes[0] / 128;
    const int e = in_sizes[1] / 2;
    const int* src = ei;
    const int* dst = ei + e;

    __half* p_hs;
    float*  p_a;
    cudaGetSymbolAddress((void**)&p_hs, g_hs);
    cudaGetSymbolAddress((void**)&p_a,  g_a);

    const int T = 256;
    const int nb = (n + SCANB - 1) / SCANB;

    // 1-3: counts, block scan, dinv (dinv only needs counts)
    k_count<<<(e + T - 1) / T, T>>>(dst, e);
    k_scan_block<<<nb, SCANB>>>(n);
    k_dinv<<<(n + T - 1) / T, T>>>(n);

    // 4: layer-1 GEMM (profiled launch)
    k_gemm_f16<<<(n + 127) / 128, T>>>(x, W1, p_hs, n, 128);

    // 5-7: finish CSR
    k_scan_tops<<<1, 128>>>(nb);
    k_finish_offsets<<<(n + T - 1) / T, T>>>(n, e);
    k_fill<<<(e + T - 1) / T, T>>>(src, dst, e);

    // 8: layer-1 aggregation
    k_agg1<<<(n * 32 + T - 1) / T, T>>>(p_hs, p_a, b1, n);

    // 9-10: layer-2 GEMM + aggregation/classifier
    k_gemm_f16<<<(n + 127) / 128, T>>>(p_a, W2, p_hs, n, 64);
    k_agg2<<<(n * 32 + T - 1) / T, T>>>(p_hs, b2, Wc, bc, logits, n);
}